// round 2
// baseline (speedup 1.0000x reference)
#include <cuda_runtime.h>
#include <math.h>

#define HIDN   2048
#define INTERN 4096
#define CONVD  6144
#define PROJN  10304
#define NHEAD  64
#define HEADP  64
#define NGRP   8
#define NSTATE 128
#define CHUNK  256
#define LSEQ   2048
#define NBATCH 2
#define NCHUNK 8
#define BT     4096          // total tokens
#define NBC    16            // NBATCH*NCHUNK
#define EPSV   1e-5f

// ---------------- scratch (device globals; no allocation) ----------------
__device__ float g_zx[(size_t)BT * PROJN];        // in_proj output
__device__ float g_xbc[(size_t)BT * CONVD];       // conv+silu output
__device__ float g_dtsp[BT * NHEAD];              // softplus(dt)
__device__ float g_dacs[BT * NHEAD];              // cumsum(dt*A) per chunk
__device__ float g_states[(size_t)NBC * NHEAD * HEADP * NSTATE];
__device__ float g_prev[(size_t)NBC * NHEAD * HEADP * NSTATE];
__device__ float g_y[(size_t)BT * INTERN];

// ---------------- GEMM: C[M,N] = A[M,K] * B[N,K]^T  (both row-major, K-contig)
// 128x128 tile, BK=8, 256 threads, 8x8 per thread.
__global__ __launch_bounds__(256) void gemm_nt(
    const float* __restrict__ A, const float* __restrict__ B,
    float* __restrict__ C, int M, int N, int K)
{
    __shared__ float As[8][128];
    __shared__ float Bs[8][128];
    int bm = blockIdx.y * 128;
    int bn = blockIdx.x * 128;
    int tid = threadIdx.x;
    int tx = tid & 15, ty = tid >> 4;

    int lr = tid & 127;            // row within tile
    int lk = (tid >> 7) * 4;       // k offset: 0 or 4
    const float* Ap = A + (size_t)(bm + lr) * K + lk;
    int brow = bn + lr;
    bool bvalid = brow < N;
    const float* Bp = B + (size_t)(bvalid ? brow : 0) * K + lk;

    float acc[8][8];
    #pragma unroll
    for (int i = 0; i < 8; i++)
        #pragma unroll
        for (int j = 0; j < 8; j++) acc[i][j] = 0.f;

    for (int k0 = 0; k0 < K; k0 += 8) {
        float4 av = *(const float4*)(Ap + k0);
        float4 bv = bvalid ? *(const float4*)(Bp + k0) : make_float4(0.f,0.f,0.f,0.f);
        As[lk+0][lr] = av.x; As[lk+1][lr] = av.y; As[lk+2][lr] = av.z; As[lk+3][lr] = av.w;
        Bs[lk+0][lr] = bv.x; Bs[lk+1][lr] = bv.y; Bs[lk+2][lr] = bv.z; Bs[lk+3][lr] = bv.w;
        __syncthreads();
        #pragma unroll
        for (int k = 0; k < 8; k++) {
            float4 a0 = *(const float4*)&As[k][ty*4];
            float4 a1 = *(const float4*)&As[k][64 + ty*4];
            float4 b0 = *(const float4*)&Bs[k][tx*4];
            float4 b1 = *(const float4*)&Bs[k][64 + tx*4];
            float ar[8] = {a0.x,a0.y,a0.z,a0.w,a1.x,a1.y,a1.z,a1.w};
            float br[8] = {b0.x,b0.y,b0.z,b0.w,b1.x,b1.y,b1.z,b1.w};
            #pragma unroll
            for (int i = 0; i < 8; i++)
                #pragma unroll
                for (int j = 0; j < 8; j++)
                    acc[i][j] += ar[i] * br[j];
        }
        __syncthreads();
    }
    #pragma unroll
    for (int ih = 0; ih < 2; ih++)
        #pragma unroll
        for (int i = 0; i < 4; i++) {
            int r = bm + ih*64 + ty*4 + i;
            #pragma unroll
            for (int jh = 0; jh < 2; jh++) {
                int c = bn + jh*64 + tx*4;
                if (c < N) {
                    float4 v = make_float4(acc[ih*4+i][jh*4+0], acc[ih*4+i][jh*4+1],
                                           acc[ih*4+i][jh*4+2], acc[ih*4+i][jh*4+3]);
                    *(float4*)&C[(size_t)r * N + c] = v;
                }
            }
        }
}

// ---------------- conv1d (K=4, causal, per-batch padding) + SiLU -------------
__global__ void conv_silu_kernel(const float* __restrict__ cw, const float* __restrict__ cb)
{
    int c = blockIdx.x * 256 + threadIdx.x;
    int t = blockIdx.y;
    if (c >= CONVD) return;
    int pos = t & (LSEQ - 1);
    const float* col = g_zx + INTERN + c;
    float w0 = cw[c*4+0], w1 = cw[c*4+1], w2 = cw[c*4+2], w3 = cw[c*4+3];
    float v = cb[c];
    float x3 = col[(size_t)t * PROJN];
    float x2 = (pos >= 1) ? col[(size_t)(t-1) * PROJN] : 0.f;
    float x1 = (pos >= 2) ? col[(size_t)(t-2) * PROJN] : 0.f;
    float x0 = (pos >= 3) ? col[(size_t)(t-3) * PROJN] : 0.f;
    v += w0*x0 + w1*x1 + w2*x2 + w3*x3;
    g_xbc[(size_t)t * CONVD + c] = v / (1.f + expf(-v));
}

// ---------------- dt: softplus + dA cumsum per chunk -------------------------
__global__ void dt_kernel(const float* __restrict__ dtb, const float* __restrict__ alog)
{
    int bc = blockIdx.x;       // 0..15
    int h = threadIdx.x;       // 0..63
    int t0 = bc * CHUNK;
    float bias = dtb[h];
    float A = -expf(alog[h]);
    float cs = 0.f;
    for (int j = 0; j < CHUNK; j++) {
        int t = t0 + j;
        float raw = g_zx[(size_t)t * PROJN + INTERN + CONVD + h] + bias;
        float dtv = (raw > 20.f) ? raw : log1pf(expf(raw));
        g_dtsp[t * NHEAD + h] = dtv;
        cs += dtv * A;
        g_dacs[t * NHEAD + h] = cs;
    }
}

// ---------------- per-chunk states: S[p,n] = sum_j x[j,p] w[j] B[j,n] --------
__global__ __launch_bounds__(256) void states_kernel()
{
    int h = blockIdx.x, bc = blockIdx.y;
    int g = h >> 3;
    int t0 = bc * CHUNK;
    int tlast = t0 + CHUNK - 1;
    __shared__ float xw[32][64];
    __shared__ float Bs[32][128];
    __shared__ float ws[32];
    int tid = threadIdx.x;
    int tp = tid & 15;     // p block of 4
    int tn = tid >> 4;     // n block of 8
    float acc[4][8];
    #pragma unroll
    for (int i = 0; i < 4; i++)
        #pragma unroll
        for (int k = 0; k < 8; k++) acc[i][k] = 0.f;
    float daL = g_dacs[tlast * NHEAD + h];

    for (int j0 = 0; j0 < CHUNK; j0 += 32) {
        if (tid < 32) {
            int t = t0 + j0 + tid;
            ws[tid] = expf(daL - g_dacs[t * NHEAD + h]) * g_dtsp[t * NHEAD + h];
        }
        __syncthreads();
        for (int e = tid; e < 32*64; e += 256) {
            int j = e >> 6, p = e & 63;
            int t = t0 + j0 + j;
            xw[j][p] = g_xbc[(size_t)t * CONVD + h * HEADP + p] * ws[j];
        }
        for (int e = tid; e < 32*128; e += 256) {
            int j = e >> 7, n = e & 127;
            int t = t0 + j0 + j;
            Bs[j][n] = g_xbc[(size_t)t * CONVD + INTERN + g * NSTATE + n];
        }
        __syncthreads();
        #pragma unroll 4
        for (int j = 0; j < 32; j++) {
            float4 xv = *(const float4*)&xw[j][tp*4];
            float4 b0 = *(const float4*)&Bs[j][tn*8];
            float4 b1 = *(const float4*)&Bs[j][tn*8+4];
            float xr[4] = {xv.x, xv.y, xv.z, xv.w};
            float br[8] = {b0.x,b0.y,b0.z,b0.w,b1.x,b1.y,b1.z,b1.w};
            #pragma unroll
            for (int i = 0; i < 4; i++)
                #pragma unroll
                for (int k = 0; k < 8; k++)
                    acc[i][k] += xr[i] * br[k];
        }
        __syncthreads();
    }
    float* S = g_states + ((size_t)bc * NHEAD + h) * HEADP * NSTATE;
    #pragma unroll
    for (int i = 0; i < 4; i++)
        #pragma unroll
        for (int k = 0; k < 8; k++)
            S[(tp*4 + i) * NSTATE + tn*8 + k] = acc[i][k];
}

// ---------------- inter-chunk scan ------------------------------------------
__global__ void scan_kernel()
{
    int b = blockIdx.x >> 6;
    int h = blockIdx.x & 63;
    for (int e = threadIdx.x; e < HEADP * NSTATE; e += 256) {
        float run = 0.f;
        for (int z = 0; z < NCHUNK; z++) {
            int bc = b * NCHUNK + z;
            size_t off = ((size_t)bc * NHEAD + h) * HEADP * NSTATE + e;
            g_prev[off] = run;
            int tlast = bc * CHUNK + CHUNK - 1;
            float dec = expf(g_dacs[tlast * NHEAD + h]);
            run = dec * run + g_states[off];
        }
    }
}

// ---------------- fused Y_diag + Y_off + D*x ---------------------------------
// block = (itile, h, bc); computes 64 tokens x 64 headdim
__global__ __launch_bounds__(256) void ymain_kernel(const float* __restrict__ Dp)
{
    int it = blockIdx.x, h = blockIdx.y, bc = blockIdx.z;
    int g = h >> 3;
    int t0 = bc * CHUNK;
    int i0 = it * 64;
    extern __shared__ float sm[];
    float* Cs  = sm;             // [64][129]
    float* Js  = Cs + 64*129;    // [64][129]  (prev or B_j)
    float* Xs  = Js + 64*129;    // [64][65]
    float* Ss  = Xs + 64*65;     // [64][65]
    float* dai = Ss + 64*65;     // [64]
    float* eiv = dai + 64;       // [64]
    float* daj = eiv + 64;       // [64]
    float* dtj = daj + 64;       // [64]

    int tid = threadIdx.x;
    int tx = tid & 15, ty = tid >> 4;

    // load C_i tile and dA_cs for i-rows
    for (int e = tid; e < 64*128; e += 256) {
        int i = e >> 7, n = e & 127;
        Cs[i*129 + n] = g_xbc[(size_t)(t0 + i0 + i) * CONVD + INTERN + NGRP*NSTATE + g*NSTATE + n];
    }
    if (tid < 64) {
        float d = g_dacs[(t0 + i0 + tid) * NHEAD + h];
        dai[tid] = d;
        eiv[tid] = expf(d);
    }
    // load prev state [p][n]
    const float* prev = g_prev + ((size_t)bc * NHEAD + h) * HEADP * NSTATE;
    for (int e = tid; e < 64*128; e += 256) {
        int p = e >> 7, n = e & 127;
        Js[p*129 + n] = prev[p * NSTATE + n];
    }
    __syncthreads();

    // Y_off: acc[i][p] = ei[i] * sum_n C[i,n]*prev[p,n]
    float acc[4][4];
    {
        float off[4][4];
        #pragma unroll
        for (int i = 0; i < 4; i++)
            #pragma unroll
            for (int p = 0; p < 4; p++) off[i][p] = 0.f;
        #pragma unroll 4
        for (int n = 0; n < 128; n++) {
            float a[4], bv[4];
            #pragma unroll
            for (int i = 0; i < 4; i++) a[i] = Cs[(ty*4 + i)*129 + n];
            #pragma unroll
            for (int p = 0; p < 4; p++) bv[p] = Js[(tx*4 + p)*129 + n];
            #pragma unroll
            for (int i = 0; i < 4; i++)
                #pragma unroll
                for (int p = 0; p < 4; p++) off[i][p] += a[i] * bv[p];
        }
        #pragma unroll
        for (int i = 0; i < 4; i++)
            #pragma unroll
            for (int p = 0; p < 4; p++) acc[i][p] = off[i][p] * eiv[ty*4 + i];
    }
    __syncthreads();

    // Y_diag: loop over j-tiles <= i-tile
    for (int jt = 0; jt <= it; jt++) {
        int j0 = jt * 64;
        for (int e = tid; e < 64*128; e += 256) {
            int j = e >> 7, n = e & 127;
            Js[j*129 + n] = g_xbc[(size_t)(t0 + j0 + j) * CONVD + INTERN + g*NSTATE + n];
        }
        for (int e = tid; e < 64*64; e += 256) {
            int j = e >> 6, p = e & 63;
            Xs[j*65 + p] = g_xbc[(size_t)(t0 + j0 + j) * CONVD + h * HEADP + p];
        }
        if (tid < 64) {
            int t = t0 + j0 + tid;
            daj[tid] = g_dacs[t * NHEAD + h];
            dtj[tid] = g_dtsp[t * NHEAD + h];
        }
        __syncthreads();

        // S = C_i . B_j^T over N=128
        float s[4][4];
        #pragma unroll
        for (int i = 0; i < 4; i++)
            #pragma unroll
            for (int j = 0; j < 4; j++) s[i][j] = 0.f;
        #pragma unroll 4
        for (int n = 0; n < 128; n++) {
            float a[4], bv[4];
            #pragma unroll
            for (int i = 0; i < 4; i++) a[i] = Cs[(ty*4 + i)*129 + n];
            #pragma unroll
            for (int j = 0; j < 4; j++) bv[j] = Js[(tx*4 + j)*129 + n];
            #pragma unroll
            for (int i = 0; i < 4; i++)
                #pragma unroll
                for (int j = 0; j < 4; j++) s[i][j] += a[i] * bv[j];
        }
        // mask + decay + dt, stage to smem
        #pragma unroll
        for (int ii = 0; ii < 4; ii++) {
            int il = ty*4 + ii;
            int ig = i0 + il;
            #pragma unroll
            for (int jj = 0; jj < 4; jj++) {
                int jl = tx*4 + jj;
                int jg = j0 + jl;
                float v = 0.f;
                if (ig >= jg) v = s[ii][jj] * expf(dai[il] - daj[jl]) * dtj[jl];
                Ss[il*65 + jl] = v;
            }
        }
        __syncthreads();
        // acc += S @ x_j
        #pragma unroll 4
        for (int j = 0; j < 64; j++) {
            float a[4], bv[4];
            #pragma unroll
            for (int i = 0; i < 4; i++) a[i] = Ss[(ty*4 + i)*65 + j];
            #pragma unroll
            for (int p = 0; p < 4; p++) bv[p] = Xs[j*65 + tx*4 + p];
            #pragma unroll
            for (int i = 0; i < 4; i++)
                #pragma unroll
                for (int p = 0; p < 4; p++) acc[i][p] += a[i] * bv[p];
        }
        __syncthreads();
    }

    // epilogue: + D[h] * x_i ; write y
    float Dh = Dp[h];
    #pragma unroll
    for (int ii = 0; ii < 4; ii++) {
        int t = t0 + i0 + ty*4 + ii;
        #pragma unroll
        for (int pp = 0; pp < 4; pp++) {
            int p = tx*4 + pp;
            float xv = g_xbc[(size_t)t * CONVD + h * HEADP + p];
            g_y[(size_t)t * INTERN + h * HEADP + p] = acc[ii][pp] + Dh * xv;
        }
    }
}

// ---------------- RMS norm + silu(z) gate (in-place on g_y) ------------------
__global__ void normgate_kernel(const float* __restrict__ nw)
{
    int t = blockIdx.x;
    float s = 0.f;
    for (int c = threadIdx.x; c < INTERN; c += 256) {
        float v = g_y[(size_t)t * INTERN + c];
        s += v * v;
    }
    __shared__ float red[8];
    #pragma unroll
    for (int o = 16; o; o >>= 1) s += __shfl_xor_sync(0xffffffffu, s, o);
    if ((threadIdx.x & 31) == 0) red[threadIdx.x >> 5] = s;
    __syncthreads();
    if (threadIdx.x < 8) {
        float v = red[threadIdx.x];
        #pragma unroll
        for (int o = 4; o; o >>= 1) v += __shfl_xor_sync(0xffu, v, o);
        if (threadIdx.x == 0) red[0] = v;
    }
    __syncthreads();
    float inv = rsqrtf(red[0] / (float)INTERN + EPSV);
    for (int c = threadIdx.x; c < INTERN; c += 256) {
        float v = g_y[(size_t)t * INTERN + c] * inv * nw[c];
        float z = g_zx[(size_t)t * PROJN + c];
        g_y[(size_t)t * INTERN + c] = v * (z / (1.f + expf(-z)));
    }
}

// ---------------- launch ------------------------------------------------------
extern "C" void kernel_launch(void* const* d_in, const int* in_sizes, int n_in,
                              void* d_out, int out_size)
{
    const float* hs    = (const float*)d_in[0];
    const float* w_in  = (const float*)d_in[1];
    const float* cw    = (const float*)d_in[2];
    const float* cb    = (const float*)d_in[3];
    const float* dtb   = (const float*)d_in[4];
    const float* alog  = (const float*)d_in[5];
    const float* Dp    = (const float*)d_in[6];
    const float* nw    = (const float*)d_in[7];
    const float* w_out = (const float*)d_in[8];
    float* out = (float*)d_out;

    float *zx, *y;
    cudaGetSymbolAddress((void**)&zx, g_zx);
    cudaGetSymbolAddress((void**)&y, g_y);

    size_t ysmem = (size_t)(64*129*2 + 64*65*2 + 4*64) * sizeof(float);
    cudaFuncSetAttribute(ymain_kernel, cudaFuncAttributeMaxDynamicSharedMemorySize, (int)ysmem);

    // 1) in_proj GEMM: [4096,10304] = [4096,2048] x [10304,2048]^T
    gemm_nt<<<dim3((PROJN + 127) / 128, BT / 128), 256>>>(hs, w_in, zx, BT, PROJN, HIDN);
    // 2) conv + silu
    conv_silu_kernel<<<dim3(CONVD / 256, BT), 256>>>(cw, cb);
    // 3) dt softplus + dA cumsum
    dt_kernel<<<NBC, NHEAD>>>(dtb, alog);
    // 4) per-chunk states
    states_kernel<<<dim3(NHEAD, NBC), 256>>>();
    // 5) inter-chunk scan
    scan_kernel<<<NBATCH * NHEAD, 256>>>();
    // 6) fused diag + off + D*x
    ymain_kernel<<<dim3(CHUNK / 64, NHEAD, NBC), 256, ysmem>>>(Dp);
    // 7) rmsnorm + gate
    normgate_kernel<<<BT, 256>>>(nw);
    // 8) out_proj GEMM: [4096,2048] = [4096,4096] x [2048,4096]^T
    gemm_nt<<<dim3(HIDN / 128, BT / 128), 256>>>(y, w_out, out, BT, HIDN, INTERN);
}

// round 6
// speedup vs baseline: 1.4054x; 1.4054x over previous
#include <cuda_runtime.h>
#include <mma.h>
#include <math.h>

using namespace nvcuda;

#define HIDN   2048
#define INTERN 4096
#define CONVD  6144
#define PROJN  10304
#define NHEAD  64
#define HEADP  64
#define NGRP   8
#define NSTATE 128
#define CHUNK  256
#define LSEQ   2048
#define NBATCH 2
#define NCHUNK 8
#define BT     4096          // total tokens
#define NBC    16            // NBATCH*NCHUNK
#define EPSV   1e-5f

// ---------------- scratch (device globals; no allocation) ----------------
__device__ float g_zx[(size_t)BT * PROJN];        // in_proj output
__device__ float g_xbc[(size_t)BT * CONVD];       // conv+silu output
__device__ float g_dtsp[BT * NHEAD];              // softplus(dt)
__device__ float g_dacs[BT * NHEAD];              // cumsum(dt*A) per chunk
__device__ float g_states[(size_t)NBC * NHEAD * HEADP * NSTATE];
__device__ float g_prev[(size_t)NBC * NHEAD * HEADP * NSTATE];
__device__ float g_y[(size_t)BT * INTERN];

__device__ __forceinline__ float to_tf32_rn(float x) {
    float r;
    asm("cvt.rna.tf32.f32 %0, %1;" : "=f"(r) : "f"(x));
    return r;
}

// ---------------- TF32 tensor-core GEMM: C[M,N] = A[M,K] * B[N,K]^T ----------
// Both A and B row-major, K contiguous. 128x128 block tile, BK=32,
// 256 threads = 8 warps, each warp 64x32 (4x2 wmma m16n16k8 tiles).
#define LDA 40
#define LDB 40

__global__ __launch_bounds__(256) void gemm_tf32(
    const float* __restrict__ A, const float* __restrict__ B,
    float* __restrict__ C, int M, int N, int K)
{
    __shared__ float As[128 * LDA];
    __shared__ float Bs[128 * LDB];

    int bm = blockIdx.y * 128;
    int bn = blockIdx.x * 128;
    int tid = threadIdx.x;
    int wid = tid >> 5;
    int wm = wid >> 2;          // 0..1  (64-row strip)
    int wn = wid & 3;           // 0..3  (32-col strip)

    // staging mapping: each thread loads 16 consecutive floats (4 x float4)
    int srow = tid >> 1;              // 0..127
    int skc  = (tid & 1) * 16;        // 0 or 16

    const float* Ag = A + (size_t)(bm + srow) * K + skc;
    int brow = bn + srow;
    bool bvalid = brow < N;
    const float* Bg = B + (size_t)(bvalid ? brow : 0) * K + skc;

    wmma::fragment<wmma::accumulator, 16, 16, 8, float> acc[4][2];
    #pragma unroll
    for (int i = 0; i < 4; i++)
        #pragma unroll
        for (int j = 0; j < 2; j++)
            wmma::fill_fragment(acc[i][j], 0.0f);

    for (int k0 = 0; k0 < K; k0 += 32) {
        // stage A
        #pragma unroll
        for (int v = 0; v < 4; v++) {
            float4 a = *(const float4*)(Ag + k0 + v * 4);
            float* d = &As[srow * LDA + skc + v * 4];
            d[0] = to_tf32_rn(a.x); d[1] = to_tf32_rn(a.y);
            d[2] = to_tf32_rn(a.z); d[3] = to_tf32_rn(a.w);
        }
        // stage B (zero-pad invalid rows)
        #pragma unroll
        for (int v = 0; v < 4; v++) {
            float4 b = bvalid ? *(const float4*)(Bg + k0 + v * 4)
                              : make_float4(0.f, 0.f, 0.f, 0.f);
            float* d = &Bs[srow * LDB + skc + v * 4];
            d[0] = to_tf32_rn(b.x); d[1] = to_tf32_rn(b.y);
            d[2] = to_tf32_rn(b.z); d[3] = to_tf32_rn(b.w);
        }
        __syncthreads();

        #pragma unroll
        for (int ks = 0; ks < 4; ks++) {
            wmma::fragment<wmma::matrix_a, 16, 16, 8, wmma::precision::tf32, wmma::row_major> af[4];
            wmma::fragment<wmma::matrix_b, 16, 16, 8, wmma::precision::tf32, wmma::col_major> bf[2];
            #pragma unroll
            for (int i = 0; i < 4; i++)
                wmma::load_matrix_sync(af[i], &As[(wm * 64 + i * 16) * LDA + ks * 8], LDA);
            #pragma unroll
            for (int j = 0; j < 2; j++)
                wmma::load_matrix_sync(bf[j], &Bs[(wn * 32 + j * 16) * LDB + ks * 8], LDB);
            #pragma unroll
            for (int i = 0; i < 4; i++)
                #pragma unroll
                for (int j = 0; j < 2; j++)
                    wmma::mma_sync(acc[i][j], af[i], bf[j], acc[i][j]);
        }
        __syncthreads();
    }

    // epilogue (N is always a multiple of 16 here: 10304, 2048)
    #pragma unroll
    for (int i = 0; i < 4; i++) {
        int r0 = bm + wm * 64 + i * 16;
        #pragma unroll
        for (int j = 0; j < 2; j++) {
            int c0 = bn + wn * 32 + j * 16;
            if (c0 < N)
                wmma::store_matrix_sync(&C[(size_t)r0 * N + c0], acc[i][j], N, wmma::mem_row_major);
        }
    }
}

// ---------------- conv1d (K=4, causal, per-batch padding) + SiLU -------------
__global__ void conv_silu_kernel(const float* __restrict__ cw, const float* __restrict__ cb)
{
    int c = blockIdx.x * 256 + threadIdx.x;
    int t = blockIdx.y;
    if (c >= CONVD) return;
    int pos = t & (LSEQ - 1);
    const float* col = g_zx + INTERN + c;
    float w0 = cw[c*4+0], w1 = cw[c*4+1], w2 = cw[c*4+2], w3 = cw[c*4+3];
    float v = cb[c];
    float x3 = col[(size_t)t * PROJN];
    float x2 = (pos >= 1) ? col[(size_t)(t-1) * PROJN] : 0.f;
    float x1 = (pos >= 2) ? col[(size_t)(t-2) * PROJN] : 0.f;
    float x0 = (pos >= 3) ? col[(size_t)(t-3) * PROJN] : 0.f;
    v += w0*x0 + w1*x1 + w2*x2 + w3*x3;
    g_xbc[(size_t)t * CONVD + c] = v / (1.f + expf(-v));
}

// ---------------- dt: softplus + dA cumsum per chunk -------------------------
__global__ void dt_kernel(const float* __restrict__ dtb, const float* __restrict__ alog)
{
    int bc = blockIdx.x;       // 0..15
    int h = threadIdx.x;       // 0..63
    int t0 = bc * CHUNK;
    float bias = dtb[h];
    float A = -expf(alog[h]);
    float cs = 0.f;
    for (int j = 0; j < CHUNK; j++) {
        int t = t0 + j;
        float raw = g_zx[(size_t)t * PROJN + INTERN + CONVD + h] + bias;
        float dtv = (raw > 20.f) ? raw : log1pf(expf(raw));
        g_dtsp[t * NHEAD + h] = dtv;
        cs += dtv * A;
        g_dacs[t * NHEAD + h] = cs;
    }
}

// ---------------- per-chunk states: S[p,n] = sum_j x[j,p] w[j] B[j,n] --------
__global__ __launch_bounds__(256) void states_kernel()
{
    int h = blockIdx.x, bc = blockIdx.y;
    int g = h >> 3;
    int t0 = bc * CHUNK;
    int tlast = t0 + CHUNK - 1;
    __shared__ float xw[32][64];
    __shared__ float Bs[32][128];
    __shared__ float ws[32];
    int tid = threadIdx.x;
    int tp = tid & 15;     // p block of 4
    int tn = tid >> 4;     // n block of 8
    float acc[4][8];
    #pragma unroll
    for (int i = 0; i < 4; i++)
        #pragma unroll
        for (int k = 0; k < 8; k++) acc[i][k] = 0.f;
    float daL = g_dacs[tlast * NHEAD + h];

    for (int j0 = 0; j0 < CHUNK; j0 += 32) {
        if (tid < 32) {
            int t = t0 + j0 + tid;
            ws[tid] = expf(daL - g_dacs[t * NHEAD + h]) * g_dtsp[t * NHEAD + h];
        }
        __syncthreads();
        for (int e = tid; e < 32*64; e += 256) {
            int j = e >> 6, p = e & 63;
            int t = t0 + j0 + j;
            xw[j][p] = g_xbc[(size_t)t * CONVD + h * HEADP + p] * ws[j];
        }
        for (int e = tid; e < 32*128; e += 256) {
            int j = e >> 7, n = e & 127;
            int t = t0 + j0 + j;
            Bs[j][n] = g_xbc[(size_t)t * CONVD + INTERN + g * NSTATE + n];
        }
        __syncthreads();
        #pragma unroll 4
        for (int j = 0; j < 32; j++) {
            float4 xv = *(const float4*)&xw[j][tp*4];
            float4 b0 = *(const float4*)&Bs[j][tn*8];
            float4 b1 = *(const float4*)&Bs[j][tn*8+4];
            float xr[4] = {xv.x, xv.y, xv.z, xv.w};
            float br[8] = {b0.x,b0.y,b0.z,b0.w,b1.x,b1.y,b1.z,b1.w};
            #pragma unroll
            for (int i = 0; i < 4; i++)
                #pragma unroll
                for (int k = 0; k < 8; k++)
                    acc[i][k] += xr[i] * br[k];
        }
        __syncthreads();
    }
    float* S = g_states + ((size_t)bc * NHEAD + h) * HEADP * NSTATE;
    #pragma unroll
    for (int i = 0; i < 4; i++)
        #pragma unroll
        for (int k = 0; k < 8; k++)
            S[(tp*4 + i) * NSTATE + tn*8 + k] = acc[i][k];
}

// ---------------- inter-chunk scan ------------------------------------------
__global__ void scan_kernel()
{
    int b = blockIdx.x >> 6;
    int h = blockIdx.x & 63;
    for (int e = threadIdx.x; e < HEADP * NSTATE; e += 256) {
        float run = 0.f;
        for (int z = 0; z < NCHUNK; z++) {
            int bc = b * NCHUNK + z;
            size_t off = ((size_t)bc * NHEAD + h) * HEADP * NSTATE + e;
            g_prev[off] = run;
            int tlast = bc * CHUNK + CHUNK - 1;
            float dec = expf(g_dacs[tlast * NHEAD + h]);
            run = dec * run + g_states[off];
        }
    }
}

// ---------------- fused Y_diag + Y_off + D*x ---------------------------------
// block = (itile, h, bc); computes 64 tokens x 64 headdim
__global__ __launch_bounds__(256) void ymain_kernel(const float* __restrict__ Dp)
{
    int it = blockIdx.x, h = blockIdx.y, bc = blockIdx.z;
    int g = h >> 3;
    int t0 = bc * CHUNK;
    int i0 = it * 64;
    extern __shared__ float sm[];
    float* Cs  = sm;             // [64][129]
    float* Js  = Cs + 64*129;    // [64][129]  (prev or B_j)
    float* Xs  = Js + 64*129;    // [64][65]
    float* Ss  = Xs + 64*65;     // [64][65]
    float* dai = Ss + 64*65;     // [64]
    float* eiv = dai + 64;       // [64]
    float* daj = eiv + 64;       // [64]
    float* dtj = daj + 64;       // [64]

    int tid = threadIdx.x;
    int tx = tid & 15, ty = tid >> 4;

    // load C_i tile and dA_cs for i-rows
    for (int e = tid; e < 64*128; e += 256) {
        int i = e >> 7, n = e & 127;
        Cs[i*129 + n] = g_xbc[(size_t)(t0 + i0 + i) * CONVD + INTERN + NGRP*NSTATE + g*NSTATE + n];
    }
    if (tid < 64) {
        float d = g_dacs[(t0 + i0 + tid) * NHEAD + h];
        dai[tid] = d;
        eiv[tid] = expf(d);
    }
    // load prev state [p][n]
    const float* prev = g_prev + ((size_t)bc * NHEAD + h) * HEADP * NSTATE;
    for (int e = tid; e < 64*128; e += 256) {
        int p = e >> 7, n = e & 127;
        Js[p*129 + n] = prev[p * NSTATE + n];
    }
    __syncthreads();

    // Y_off: acc[i][p] = ei[i] * sum_n C[i,n]*prev[p,n]
    float acc[4][4];
    {
        float off[4][4];
        #pragma unroll
        for (int i = 0; i < 4; i++)
            #pragma unroll
            for (int p = 0; p < 4; p++) off[i][p] = 0.f;
        #pragma unroll 4
        for (int n = 0; n < 128; n++) {
            float a[4], bv[4];
            #pragma unroll
            for (int i = 0; i < 4; i++) a[i] = Cs[(ty*4 + i)*129 + n];
            #pragma unroll
            for (int p = 0; p < 4; p++) bv[p] = Js[(tx*4 + p)*129 + n];
            #pragma unroll
            for (int i = 0; i < 4; i++)
                #pragma unroll
                for (int p = 0; p < 4; p++) off[i][p] += a[i] * bv[p];
        }
        #pragma unroll
        for (int i = 0; i < 4; i++)
            #pragma unroll
            for (int p = 0; p < 4; p++) acc[i][p] = off[i][p] * eiv[ty*4 + i];
    }
    __syncthreads();

    // Y_diag: loop over j-tiles <= i-tile
    for (int jt = 0; jt <= it; jt++) {
        int j0 = jt * 64;
        for (int e = tid; e < 64*128; e += 256) {
            int j = e >> 7, n = e & 127;
            Js[j*129 + n] = g_xbc[(size_t)(t0 + j0 + j) * CONVD + INTERN + g*NSTATE + n];
        }
        for (int e = tid; e < 64*64; e += 256) {
            int j = e >> 6, p = e & 63;
            Xs[j*65 + p] = g_xbc[(size_t)(t0 + j0 + j) * CONVD + h * HEADP + p];
        }
        if (tid < 64) {
            int t = t0 + j0 + tid;
            daj[tid] = g_dacs[t * NHEAD + h];
            dtj[tid] = g_dtsp[t * NHEAD + h];
        }
        __syncthreads();

        // S = C_i . B_j^T over N=128
        float s[4][4];
        #pragma unroll
        for (int i = 0; i < 4; i++)
            #pragma unroll
            for (int j = 0; j < 4; j++) s[i][j] = 0.f;
        #pragma unroll 4
        for (int n = 0; n < 128; n++) {
            float a[4], bv[4];
            #pragma unroll
            for (int i = 0; i < 4; i++) a[i] = Cs[(ty*4 + i)*129 + n];
            #pragma unroll
            for (int j = 0; j < 4; j++) bv[j] = Js[(tx*4 + j)*129 + n];
            #pragma unroll
            for (int i = 0; i < 4; i++)
                #pragma unroll
                for (int j = 0; j < 4; j++) s[i][j] += a[i] * bv[j];
        }
        // mask + decay + dt, stage to smem
        #pragma unroll
        for (int ii = 0; ii < 4; ii++) {
            int il = ty*4 + ii;
            int ig = i0 + il;
            #pragma unroll
            for (int jj = 0; jj < 4; jj++) {
                int jl = tx*4 + jj;
                int jg = j0 + jl;
                float v = 0.f;
                if (ig >= jg) v = s[ii][jj] * expf(dai[il] - daj[jl]) * dtj[jl];
                Ss[il*65 + jl] = v;
            }
        }
        __syncthreads();
        // acc += S @ x_j
        #pragma unroll 4
        for (int j = 0; j < 64; j++) {
            float a[4], bv[4];
            #pragma unroll
            for (int i = 0; i < 4; i++) a[i] = Ss[(ty*4 + i)*65 + j];
            #pragma unroll
            for (int p = 0; p < 4; p++) bv[p] = Xs[j*65 + tx*4 + p];
            #pragma unroll
            for (int i = 0; i < 4; i++)
                #pragma unroll
                for (int p = 0; p < 4; p++) acc[i][p] += a[i] * bv[p];
        }
        __syncthreads();
    }

    // epilogue: + D[h] * x_i ; write y
    float Dh = Dp[h];
    #pragma unroll
    for (int ii = 0; ii < 4; ii++) {
        int t = t0 + i0 + ty*4 + ii;
        #pragma unroll
        for (int pp = 0; pp < 4; pp++) {
            int p = tx*4 + pp;
            float xv = g_xbc[(size_t)t * CONVD + h * HEADP + p];
            g_y[(size_t)t * INTERN + h * HEADP + p] = acc[ii][pp] + Dh * xv;
        }
    }
}

// ---------------- RMS norm + silu(z) gate (in-place on g_y) ------------------
__global__ void normgate_kernel(const float* __restrict__ nw)
{
    int t = blockIdx.x;
    float s = 0.f;
    for (int c = threadIdx.x; c < INTERN; c += 256) {
        float v = g_y[(size_t)t * INTERN + c];
        s += v * v;
    }
    __shared__ float red[8];
    #pragma unroll
    for (int o = 16; o; o >>= 1) s += __shfl_xor_sync(0xffffffffu, s, o);
    if ((threadIdx.x & 31) == 0) red[threadIdx.x >> 5] = s;
    __syncthreads();
    if (threadIdx.x < 8) {
        float v = red[threadIdx.x];
        #pragma unroll
        for (int o = 4; o; o >>= 1) v += __shfl_xor_sync(0xffu, v, o);
        if (threadIdx.x == 0) red[0] = v;
    }
    __syncthreads();
    float inv = rsqrtf(red[0] / (float)INTERN + EPSV);
    for (int c = threadIdx.x; c < INTERN; c += 256) {
        float v = g_y[(size_t)t * INTERN + c] * inv * nw[c];
        float z = g_zx[(size_t)t * PROJN + c];
        g_y[(size_t)t * INTERN + c] = v * (z / (1.f + expf(-z)));
    }
}

// ---------------- launch ------------------------------------------------------
extern "C" void kernel_launch(void* const* d_in, const int* in_sizes, int n_in,
                              void* d_out, int out_size)
{
    const float* hs    = (const float*)d_in[0];
    const float* w_in  = (const float*)d_in[1];
    const float* cw    = (const float*)d_in[2];
    const float* cb    = (const float*)d_in[3];
    const float* dtb   = (const float*)d_in[4];
    const float* alog  = (const float*)d_in[5];
    const float* Dp    = (const float*)d_in[6];
    const float* nw    = (const float*)d_in[7];
    const float* w_out = (const float*)d_in[8];
    float* out = (float*)d_out;

    float *zx, *y;
    cudaGetSymbolAddress((void**)&zx, g_zx);
    cudaGetSymbolAddress((void**)&y, g_y);

    size_t ysmem = (size_t)(64*129*2 + 64*65*2 + 4*64) * sizeof(float);
    cudaFuncSetAttribute(ymain_kernel, cudaFuncAttributeMaxDynamicSharedMemorySize, (int)ysmem);

    // 1) in_proj GEMM: [4096,10304] = [4096,2048] x [10304,2048]^T  (tf32 TC)
    gemm_tf32<<<dim3((PROJN + 127) / 128, BT / 128), 256>>>(hs, w_in, zx, BT, PROJN, HIDN);
    // 2) conv + silu
    conv_silu_kernel<<<dim3(CONVD / 256, BT), 256>>>(cw, cb);
    // 3) dt softplus + dA cumsum
    dt_kernel<<<NBC, NHEAD>>>(dtb, alog);
    // 4) per-chunk states
    states_kernel<<<dim3(NHEAD, NBC), 256>>>();
    // 5) inter-chunk scan
    scan_kernel<<<NBATCH * NHEAD, 256>>>();
    // 6) fused diag + off + D*x
    ymain_kernel<<<dim3(CHUNK / 64, NHEAD, NBC), 256, ysmem>>>(Dp);
    // 7) rmsnorm + gate
    normgate_kernel<<<BT, 256>>>(nw);
    // 8) out_proj GEMM: [4096,2048] = [4096,4096] x [2048,4096]^T  (tf32 TC)
    gemm_tf32<<<dim3(HIDN / 128, BT / 128), 256>>>(y, w_out, out, BT, HIDN, INTERN);
}